// round 2
// baseline (speedup 1.0000x reference)
#include <cuda_runtime.h>

// ---------------------------------------------------------------------------
// LSTMActor: B=262144 samples, obs[74] -> 2-layer LSTM (H1=8,H2=16,T=24)
//            -> FC1(386->128)+ReLU -> FC2(128->24) -> softsign
// One thread per sample. FC1 accumulation fused into the timestep loop.
// All hot FMAs use packed fma.rn.f32x2 (2 MACs/instr).
// ---------------------------------------------------------------------------

#define TT   24
#define DD   3
#define OBSC 74

// ---- packed small-weight layout offsets (in floats, inside g_small/smem) ----
// PK1  : [k=0..10][p=0..3][8]   LSTM1 gate-pair interleave (i0,i1,f0,f1,g0,g1,o0,o1)
// PK2  : [k=0..23][p=0..7][8]   LSTM2 same
// B1P  : [p=0..3][8]            LSTM1 bias pairs
// B2P  : [p=0..7][8]            LSTM2 bias pairs
// PINIT: [3][128]               fc1_b ; fc1_w[:,384] ; fc1_w[:,385]
// PFC2 : [j=0..127][24]         fc2_w transposed
// FB2  : [24]                   fc2_b
#define OFF_PK1   0
#define OFF_PK2   352
#define OFF_B1P   1888
#define OFF_B2P   1920
#define OFF_PINIT 1984
#define OFF_PFC2  2368
#define OFF_FB2   5440
#define SMALL_TOT 5464

#define PACKFC_FLOATS (24*16*128)   // [t][k][j]

__device__ float4 g_packfc4[PACKFC_FLOATS/4];
__device__ __align__(16) float g_small[SMALL_TOT];

// ---------------------------------------------------------------------------
__global__ void pack_kernel(
    const float* __restrict__ w_ih1, const float* __restrict__ w_hh1,
    const float* __restrict__ b_ih1, const float* __restrict__ b_hh1,
    const float* __restrict__ w_ih2, const float* __restrict__ w_hh2,
    const float* __restrict__ b_ih2, const float* __restrict__ b_hh2,
    const float* __restrict__ fc1_w, const float* __restrict__ fc1_b,
    const float* __restrict__ fc2_w, const float* __restrict__ fc2_b)
{
    int i = blockIdx.x * blockDim.x + threadIdx.x;
    if (i < PACKFC_FLOATS) {
        int t = i >> 11;          // / 2048
        int k = (i >> 7) & 15;
        int j = i & 127;
        ((float*)g_packfc4)[i] = fc1_w[j * 386 + t * 16 + k];
    }
    int s = i - PACKFC_FLOATS;
    if (s >= 0 && s < SMALL_TOT) {
        float v;
        if (s < 352) {                       // PK1
            int k = s / 32, r = s % 32, p = r / 8, q = r % 8;
            int g = q / 2, e = q & 1, u = 2 * p + e, row = g * 8 + u;
            v = (k < 3) ? w_ih1[row * 3 + k] : w_hh1[row * 8 + (k - 3)];
        } else if (s < 1888) {               // PK2
            int z = s - 352;
            int k = z / 64, r = z % 64, p = r / 8, q = r % 8;
            int g = q / 2, e = q & 1, u = 2 * p + e, row = g * 16 + u;
            v = (k < 8) ? w_ih2[row * 8 + k] : w_hh2[row * 16 + (k - 8)];
        } else if (s < 1920) {               // B1P
            int z = s - 1888;
            int p = z / 8, q = z % 8, g = q / 2, e = q & 1;
            int row = g * 8 + (2 * p + e);
            v = b_ih1[row] + b_hh1[row];
        } else if (s < 1984) {               // B2P
            int z = s - 1920;
            int p = z / 8, q = z % 8, g = q / 2, e = q & 1;
            int row = g * 16 + (2 * p + e);
            v = b_ih2[row] + b_hh2[row];
        } else if (s < 2368) {               // PINIT
            int z = s - 1984;
            int r = z / 128, j = z % 128;
            v = (r == 0) ? fc1_b[j] : fc1_w[j * 386 + 384 + (r - 1)];
        } else if (s < 5440) {               // PFC2
            int z = s - 2368;
            int j = z / 24, a = z % 24;
            v = fc2_w[a * 128 + j];
        } else {                             // FB2
            v = fc2_b[s - 5440];
        }
        g_small[s] = v;
    }
}

// ---------------------------------------------------------------------------
__device__ __forceinline__ float2 ffma2(float2 a, float2 b, float2 c)
{
    unsigned long long ra = *reinterpret_cast<unsigned long long*>(&a);
    unsigned long long rb = *reinterpret_cast<unsigned long long*>(&b);
    unsigned long long rc = *reinterpret_cast<unsigned long long*>(&c);
    unsigned long long rd;
    asm("fma.rn.f32x2 %0, %1, %2, %3;" : "=l"(rd) : "l"(ra), "l"(rb), "l"(rc));
    return *reinterpret_cast<float2*>(&rd);
}

__device__ __forceinline__ float sigm(float x)
{
    return __fdividef(1.0f, 1.0f + __expf(-x));
}

__device__ __forceinline__ float tanh_f(float x)
{
    float ax = fabsf(x);
    float e  = __expf(-2.0f * ax);
    float r  = __fdividef(1.0f - e, 1.0f + e);
    return copysignf(r, x);
}

// ---------------------------------------------------------------------------
__global__ __launch_bounds__(256, 1) void lstm_actor_kernel(
    const float* __restrict__ obs, float* __restrict__ out, int n)
{
    __shared__ __align__(16) float sm[SMALL_TOT];
    for (int i = threadIdx.x; i < SMALL_TOT; i += 256) sm[i] = g_small[i];
    __syncthreads();

    int tid = blockIdx.x * 256 + threadIdx.x;
    if (tid >= n) return;

    const float* orow = obs + tid * OBSC;
    float x2a = orow[72];
    float x2b = orow[73];

    // FC1 accumulators (128 outputs as 64 float2), pre-seeded with bias + x2 part
    float2 acc[64];
    #pragma unroll
    for (int jq = 0; jq < 64; jq++) {
        int j0 = 2 * jq;
        float a0 = sm[OFF_PINIT + j0]     + x2a * sm[OFF_PINIT + 128 + j0]     + x2b * sm[OFF_PINIT + 256 + j0];
        float a1 = sm[OFF_PINIT + j0 + 1] + x2a * sm[OFF_PINIT + 128 + j0 + 1] + x2b * sm[OFF_PINIT + 256 + j0 + 1];
        acc[jq] = make_float2(a0, a1);
    }

    // kh[0..7] = h1, kh[8..23] = h2 (previous step)
    float kh[24];
    float c1[8];
    float c2[16];
    #pragma unroll
    for (int i = 0; i < 24; i++) kh[i] = 0.0f;
    #pragma unroll
    for (int i = 0; i < 8; i++)  c1[i] = 0.0f;
    #pragma unroll
    for (int i = 0; i < 16; i++) c2[i] = 0.0f;

    #pragma unroll 1
    for (int t = 0; t < TT; t++) {
        float xv0 = orow[t];
        float xv1 = orow[24 + t];
        float xv2 = orow[48 + t];

        // ---------------- LSTM1 (H1=8, 4 unit-pairs) ----------------
        float h1n[8];
        #pragma unroll
        for (int p = 0; p < 4; p++) {
            const float2* bp = reinterpret_cast<const float2*>(&sm[OFF_B1P + p * 8]);
            float2 gi = bp[0], gf = bp[1], gg = bp[2], go = bp[3];
            #pragma unroll
            for (int k = 0; k < 11; k++) {
                float xk = (k == 0) ? xv0 : (k == 1) ? xv1 : (k == 2) ? xv2 : kh[k - 3];
                float2 bb = make_float2(xk, xk);
                const float4* w4 = reinterpret_cast<const float4*>(&sm[OFF_PK1 + (k * 4 + p) * 8]);
                float4 wa = w4[0];
                float4 wb = w4[1];
                gi = ffma2(make_float2(wa.x, wa.y), bb, gi);
                gf = ffma2(make_float2(wa.z, wa.w), bb, gf);
                gg = ffma2(make_float2(wb.x, wb.y), bb, gg);
                go = ffma2(make_float2(wb.z, wb.w), bb, go);
            }
            {
                int u = 2 * p;
                float cn = sigm(gf.x) * c1[u] + sigm(gi.x) * tanh_f(gg.x);
                c1[u] = cn;
                h1n[u] = sigm(go.x) * tanh_f(cn);
            }
            {
                int u = 2 * p + 1;
                float cn = sigm(gf.y) * c1[u] + sigm(gi.y) * tanh_f(gg.y);
                c1[u] = cn;
                h1n[u] = sigm(go.y) * tanh_f(cn);
            }
        }
        #pragma unroll
        for (int u = 0; u < 8; u++) kh[u] = h1n[u];

        // ---------------- LSTM2 (H2=16, 8 unit-pairs) ----------------
        float h2n[16];
        #pragma unroll
        for (int p = 0; p < 8; p++) {
            const float2* bp = reinterpret_cast<const float2*>(&sm[OFF_B2P + p * 8]);
            float2 gi = bp[0], gf = bp[1], gg = bp[2], go = bp[3];
            #pragma unroll
            for (int k = 0; k < 24; k++) {
                float2 bb = make_float2(kh[k], kh[k]);
                const float4* w4 = reinterpret_cast<const float4*>(&sm[OFF_PK2 + (k * 8 + p) * 8]);
                float4 wa = w4[0];
                float4 wb = w4[1];
                gi = ffma2(make_float2(wa.x, wa.y), bb, gi);
                gf = ffma2(make_float2(wa.z, wa.w), bb, gf);
                gg = ffma2(make_float2(wb.x, wb.y), bb, gg);
                go = ffma2(make_float2(wb.z, wb.w), bb, go);
            }
            {
                int u = 2 * p;
                float cn = sigm(gf.x) * c2[u] + sigm(gi.x) * tanh_f(gg.x);
                c2[u] = cn;
                h2n[u] = sigm(go.x) * tanh_f(cn);
            }
            {
                int u = 2 * p + 1;
                float cn = sigm(gf.y) * c2[u] + sigm(gi.y) * tanh_f(gg.y);
                c2[u] = cn;
                h2n[u] = sigm(go.y) * tanh_f(cn);
            }
        }
        #pragma unroll
        for (int u = 0; u < 16; u++) kh[8 + u] = h2n[u];

        // ---------------- FC1 partial accumulation for this timestep ----------------
        const float4* wf = g_packfc4 + t * 512;   // 2048 floats per t
        #pragma unroll
        for (int k = 0; k < 16; k++) {
            float2 bb = make_float2(h2n[k], h2n[k]);
            #pragma unroll
            for (int q = 0; q < 32; q++) {
                float4 w = wf[k * 32 + q];
                acc[2 * q]     = ffma2(make_float2(w.x, w.y), bb, acc[2 * q]);
                acc[2 * q + 1] = ffma2(make_float2(w.z, w.w), bb, acc[2 * q + 1]);
            }
        }
    }

    // ---------------- ReLU + FC2 ----------------
    float2 y[12];
    #pragma unroll
    for (int m = 0; m < 12; m++)
        y[m] = make_float2(sm[OFF_FB2 + 2 * m], sm[OFF_FB2 + 2 * m + 1]);

    #pragma unroll
    for (int j = 0; j < 128; j++) {
        float xv = (j & 1) ? acc[j >> 1].y : acc[j >> 1].x;
        float xr = fmaxf(xv, 0.0f);
        float2 bb = make_float2(xr, xr);
        const float4* w4 = reinterpret_cast<const float4*>(&sm[OFF_PFC2 + j * 24]);
        #pragma unroll
        for (int m6 = 0; m6 < 6; m6++) {
            float4 w = w4[m6];
            y[2 * m6]     = ffma2(make_float2(w.x, w.y), bb, y[2 * m6]);
            y[2 * m6 + 1] = ffma2(make_float2(w.z, w.w), bb, y[2 * m6 + 1]);
        }
    }

    // ---------------- softsign + store ----------------
    float* op = out + tid * 24;
    #pragma unroll
    for (int m = 0; m < 12; m++) {
        float vx = y[m].x;
        float vy = y[m].y;
        float2 o2;
        o2.x = __fdividef(vx, 1.0f + fabsf(vx));
        o2.y = __fdividef(vy, 1.0f + fabsf(vy));
        *reinterpret_cast<float2*>(op + 2 * m) = o2;
    }
}

// ---------------------------------------------------------------------------
extern "C" void kernel_launch(void* const* d_in, const int* in_sizes, int n_in,
                              void* d_out, int out_size)
{
    const float* obs   = (const float*)d_in[0];
    const float* w_ih1 = (const float*)d_in[1];
    const float* w_hh1 = (const float*)d_in[2];
    const float* b_ih1 = (const float*)d_in[3];
    const float* b_hh1 = (const float*)d_in[4];
    const float* w_ih2 = (const float*)d_in[5];
    const float* w_hh2 = (const float*)d_in[6];
    const float* b_ih2 = (const float*)d_in[7];
    const float* b_hh2 = (const float*)d_in[8];
    const float* fc1_w = (const float*)d_in[9];
    const float* fc1_b = (const float*)d_in[10];
    const float* fc2_w = (const float*)d_in[11];
    const float* fc2_b = (const float*)d_in[12];

    int n = in_sizes[0] / OBSC;

    int pack_items = PACKFC_FLOATS + SMALL_TOT;
    int pack_blocks = (pack_items + 255) / 256;
    pack_kernel<<<pack_blocks, 256>>>(w_ih1, w_hh1, b_ih1, b_hh1,
                                      w_ih2, w_hh2, b_ih2, b_hh2,
                                      fc1_w, fc1_b, fc2_w, fc2_b);

    int grid = (n + 255) / 256;
    lstm_actor_kernel<<<grid, 256>>>(obs, (float*)d_out, n);
}

// round 3
// speedup vs baseline: 1.1472x; 1.1472x over previous
#include <cuda_runtime.h>

// ---------------------------------------------------------------------------
// LSTMActor: B=262144 samples, obs[74] -> 2-layer LSTM (H1=8,H2=16,T=24)
//            -> FC1(386->128)+ReLU -> FC2(128->24) -> softsign
// One thread per sample. FC1 accumulation fused into the timestep loop.
// R3: FC1 weight table (192 KB) staged in dynamic shared memory -> all hot
//     loads are LDS (29 cyc) instead of L2/DRAM LDG (234-577 cyc).
// ---------------------------------------------------------------------------

#define TT   24
#define OBSC 74

// ---- packed small-weight layout offsets (floats) ----
#define OFF_PK1   0
#define OFF_PK2   352
#define OFF_B1P   1888
#define OFF_B2P   1920
#define OFF_PINIT 1984
#define OFF_PFC2  2368
#define OFF_FB2   5440
#define SMALL_TOT 5464            // floats (= 21856 B, 16B-aligned)

#define PACKFC_FLOATS (24*16*128) // [t][k][j] = 49152 floats = 192 KB
#define SMEM_BYTES (SMALL_TOT*4 + PACKFC_FLOATS*4)   // 218464 B

__device__ float4 g_packfc4[PACKFC_FLOATS/4];
__device__ __align__(16) float g_small[SMALL_TOT];

// ---------------------------------------------------------------------------
__global__ void pack_kernel(
    const float* __restrict__ w_ih1, const float* __restrict__ w_hh1,
    const float* __restrict__ b_ih1, const float* __restrict__ b_hh1,
    const float* __restrict__ w_ih2, const float* __restrict__ w_hh2,
    const float* __restrict__ b_ih2, const float* __restrict__ b_hh2,
    const float* __restrict__ fc1_w, const float* __restrict__ fc1_b,
    const float* __restrict__ fc2_w, const float* __restrict__ fc2_b)
{
    int i = blockIdx.x * blockDim.x + threadIdx.x;
    if (i < PACKFC_FLOATS) {
        int t = i >> 11;
        int k = (i >> 7) & 15;
        int j = i & 127;
        ((float*)g_packfc4)[i] = fc1_w[j * 386 + t * 16 + k];
    }
    int s = i - PACKFC_FLOATS;
    if (s >= 0 && s < SMALL_TOT) {
        float v;
        if (s < 352) {                       // PK1
            int k = s / 32, r = s % 32, p = r / 8, q = r % 8;
            int g = q / 2, e = q & 1, u = 2 * p + e, row = g * 8 + u;
            v = (k < 3) ? w_ih1[row * 3 + k] : w_hh1[row * 8 + (k - 3)];
        } else if (s < 1888) {               // PK2
            int z = s - 352;
            int k = z / 64, r = z % 64, p = r / 8, q = r % 8;
            int g = q / 2, e = q & 1, u = 2 * p + e, row = g * 16 + u;
            v = (k < 8) ? w_ih2[row * 8 + k] : w_hh2[row * 16 + (k - 8)];
        } else if (s < 1920) {               // B1P
            int z = s - 1888;
            int p = z / 8, q = z % 8, g = q / 2, e = q & 1;
            int row = g * 8 + (2 * p + e);
            v = b_ih1[row] + b_hh1[row];
        } else if (s < 1984) {               // B2P
            int z = s - 1920;
            int p = z / 8, q = z % 8, g = q / 2, e = q & 1;
            int row = g * 16 + (2 * p + e);
            v = b_ih2[row] + b_hh2[row];
        } else if (s < 2368) {               // PINIT
            int z = s - 1984;
            int r = z / 128, j = z % 128;
            v = (r == 0) ? fc1_b[j] : fc1_w[j * 386 + 384 + (r - 1)];
        } else if (s < 5440) {               // PFC2
            int z = s - 2368;
            int j = z / 24, a = z % 24;
            v = fc2_w[a * 128 + j];
        } else {                             // FB2
            v = fc2_b[s - 5440];
        }
        g_small[s] = v;
    }
}

// ---------------------------------------------------------------------------
__device__ __forceinline__ float2 ffma2(float2 a, float2 b, float2 c)
{
    unsigned long long ra = *reinterpret_cast<unsigned long long*>(&a);
    unsigned long long rb = *reinterpret_cast<unsigned long long*>(&b);
    unsigned long long rc = *reinterpret_cast<unsigned long long*>(&c);
    unsigned long long rd;
    asm("fma.rn.f32x2 %0, %1, %2, %3;" : "=l"(rd) : "l"(ra), "l"(rb), "l"(rc));
    return *reinterpret_cast<float2*>(&rd);
}

__device__ __forceinline__ float sigm(float x)
{
    return __fdividef(1.0f, 1.0f + __expf(-x));
}

__device__ __forceinline__ float tanh_f(float x)
{
    float ax = fabsf(x);
    float e  = __expf(-2.0f * ax);
    float r  = __fdividef(1.0f - e, 1.0f + e);
    return copysignf(r, x);
}

// ---------------------------------------------------------------------------
__global__ __launch_bounds__(256, 1) void lstm_actor_kernel(
    const float* __restrict__ obs, float* __restrict__ out, int n)
{
    extern __shared__ __align__(16) float sm[];          // [SMALL_TOT | FC1 table]
    float4* smfc4 = reinterpret_cast<float4*>(sm + SMALL_TOT);

    // stage small table
    for (int i = threadIdx.x; i < SMALL_TOT; i += 256) sm[i] = g_small[i];
    // stage FC1 table (49152/4 = 12288 float4, 48 per thread)
    {
        const float4* src = g_packfc4;
        #pragma unroll 4
        for (int i = threadIdx.x; i < PACKFC_FLOATS / 4; i += 256)
            smfc4[i] = src[i];
    }
    __syncthreads();

    int tid = blockIdx.x * 256 + threadIdx.x;
    if (tid >= n) return;

    const float* orow = obs + tid * OBSC;
    float x2a = orow[72];
    float x2b = orow[73];

    // FC1 accumulators (128 outputs as 64 float2), pre-seeded with bias + x2 part
    float2 acc[64];
    #pragma unroll
    for (int jq = 0; jq < 64; jq++) {
        int j0 = 2 * jq;
        float a0 = sm[OFF_PINIT + j0]     + x2a * sm[OFF_PINIT + 128 + j0]     + x2b * sm[OFF_PINIT + 256 + j0];
        float a1 = sm[OFF_PINIT + j0 + 1] + x2a * sm[OFF_PINIT + 128 + j0 + 1] + x2b * sm[OFF_PINIT + 256 + j0 + 1];
        acc[jq] = make_float2(a0, a1);
    }

    // kh[0..7] = h1, kh[8..23] = h2 (previous step)
    float kh[24];
    float c1[8];
    float c2[16];
    #pragma unroll
    for (int i = 0; i < 24; i++) kh[i] = 0.0f;
    #pragma unroll
    for (int i = 0; i < 8; i++)  c1[i] = 0.0f;
    #pragma unroll
    for (int i = 0; i < 16; i++) c2[i] = 0.0f;

    #pragma unroll 1
    for (int t = 0; t < TT; t++) {
        float xv0 = orow[t];
        float xv1 = orow[24 + t];
        float xv2 = orow[48 + t];

        // ---------------- LSTM1 (H1=8, 4 unit-pairs) ----------------
        float h1n[8];
        #pragma unroll
        for (int p = 0; p < 4; p++) {
            const float2* bp = reinterpret_cast<const float2*>(&sm[OFF_B1P + p * 8]);
            float2 gi = bp[0], gf = bp[1], gg = bp[2], go = bp[3];
            #pragma unroll
            for (int k = 0; k < 11; k++) {
                float xk = (k == 0) ? xv0 : (k == 1) ? xv1 : (k == 2) ? xv2 : kh[k - 3];
                float2 bb = make_float2(xk, xk);
                const float4* w4 = reinterpret_cast<const float4*>(&sm[OFF_PK1 + (k * 4 + p) * 8]);
                float4 wa = w4[0];
                float4 wb = w4[1];
                gi = ffma2(make_float2(wa.x, wa.y), bb, gi);
                gf = ffma2(make_float2(wa.z, wa.w), bb, gf);
                gg = ffma2(make_float2(wb.x, wb.y), bb, gg);
                go = ffma2(make_float2(wb.z, wb.w), bb, go);
            }
            {
                int u = 2 * p;
                float cn = sigm(gf.x) * c1[u] + sigm(gi.x) * tanh_f(gg.x);
                c1[u] = cn;
                h1n[u] = sigm(go.x) * tanh_f(cn);
            }
            {
                int u = 2 * p + 1;
                float cn = sigm(gf.y) * c1[u] + sigm(gi.y) * tanh_f(gg.y);
                c1[u] = cn;
                h1n[u] = sigm(go.y) * tanh_f(cn);
            }
        }
        #pragma unroll
        for (int u = 0; u < 8; u++) kh[u] = h1n[u];

        // ---------------- LSTM2 (H2=16, 8 unit-pairs) ----------------
        float h2n[16];
        #pragma unroll
        for (int p = 0; p < 8; p++) {
            const float2* bp = reinterpret_cast<const float2*>(&sm[OFF_B2P + p * 8]);
            float2 gi = bp[0], gf = bp[1], gg = bp[2], go = bp[3];
            #pragma unroll
            for (int k = 0; k < 24; k++) {
                float2 bb = make_float2(kh[k], kh[k]);
                const float4* w4 = reinterpret_cast<const float4*>(&sm[OFF_PK2 + (k * 8 + p) * 8]);
                float4 wa = w4[0];
                float4 wb = w4[1];
                gi = ffma2(make_float2(wa.x, wa.y), bb, gi);
                gf = ffma2(make_float2(wa.z, wa.w), bb, gf);
                gg = ffma2(make_float2(wb.x, wb.y), bb, gg);
                go = ffma2(make_float2(wb.z, wb.w), bb, go);
            }
            {
                int u = 2 * p;
                float cn = sigm(gf.x) * c2[u] + sigm(gi.x) * tanh_f(gg.x);
                c2[u] = cn;
                h2n[u] = sigm(go.x) * tanh_f(cn);
            }
            {
                int u = 2 * p + 1;
                float cn = sigm(gf.y) * c2[u] + sigm(gi.y) * tanh_f(gg.y);
                c2[u] = cn;
                h2n[u] = sigm(go.y) * tanh_f(cn);
            }
        }
        #pragma unroll
        for (int u = 0; u < 16; u++) kh[8 + u] = h2n[u];

        // ---------------- FC1 partial accumulation (weights now in smem) ----------------
        const float4* wf = smfc4 + t * 512;   // 2048 floats per t
        #pragma unroll
        for (int k = 0; k < 16; k++) {
            float2 bb = make_float2(h2n[k], h2n[k]);
            #pragma unroll
            for (int q = 0; q < 32; q++) {
                float4 w = wf[k * 32 + q];
                acc[2 * q]     = ffma2(make_float2(w.x, w.y), bb, acc[2 * q]);
                acc[2 * q + 1] = ffma2(make_float2(w.z, w.w), bb, acc[2 * q + 1]);
            }
        }
    }

    // ---------------- ReLU + FC2 ----------------
    float2 y[12];
    #pragma unroll
    for (int m = 0; m < 12; m++)
        y[m] = make_float2(sm[OFF_FB2 + 2 * m], sm[OFF_FB2 + 2 * m + 1]);

    #pragma unroll
    for (int j = 0; j < 128; j++) {
        float xv = (j & 1) ? acc[j >> 1].y : acc[j >> 1].x;
        float xr = fmaxf(xv, 0.0f);
        float2 bb = make_float2(xr, xr);
        const float4* w4 = reinterpret_cast<const float4*>(&sm[OFF_PFC2 + j * 24]);
        #pragma unroll
        for (int m6 = 0; m6 < 6; m6++) {
            float4 w = w4[m6];
            y[2 * m6]     = ffma2(make_float2(w.x, w.y), bb, y[2 * m6]);
            y[2 * m6 + 1] = ffma2(make_float2(w.z, w.w), bb, y[2 * m6 + 1]);
        }
    }

    // ---------------- softsign + store ----------------
    float* op = out + tid * 24;
    #pragma unroll
    for (int m = 0; m < 12; m++) {
        float vx = y[m].x;
        float vy = y[m].y;
        float2 o2;
        o2.x = __fdividef(vx, 1.0f + fabsf(vx));
        o2.y = __fdividef(vy, 1.0f + fabsf(vy));
        *reinterpret_cast<float2*>(op + 2 * m) = o2;
    }
}

// ---------------------------------------------------------------------------
extern "C" void kernel_launch(void* const* d_in, const int* in_sizes, int n_in,
                              void* d_out, int out_size)
{
    const float* obs   = (const float*)d_in[0];
    const float* w_ih1 = (const float*)d_in[1];
    const float* w_hh1 = (const float*)d_in[2];
    const float* b_ih1 = (const float*)d_in[3];
    const float* b_hh1 = (const float*)d_in[4];
    const float* w_ih2 = (const float*)d_in[5];
    const float* w_hh2 = (const float*)d_in[6];
    const float* b_ih2 = (const float*)d_in[7];
    const float* b_hh2 = (const float*)d_in[8];
    const float* fc1_w = (const float*)d_in[9];
    const float* fc1_b = (const float*)d_in[10];
    const float* fc2_w = (const float*)d_in[11];
    const float* fc2_b = (const float*)d_in[12];

    int n = in_sizes[0] / OBSC;

    static bool attr_set = false;
    if (!attr_set) {
        cudaFuncSetAttribute(lstm_actor_kernel,
                             cudaFuncAttributeMaxDynamicSharedMemorySize,
                             SMEM_BYTES);
        attr_set = true;
    }

    int pack_items = PACKFC_FLOATS + SMALL_TOT;
    int pack_blocks = (pack_items + 255) / 256;
    pack_kernel<<<pack_blocks, 256>>>(w_ih1, w_hh1, b_ih1, b_hh1,
                                      w_ih2, w_hh2, b_ih2, b_hh2,
                                      fc1_w, fc1_b, fc2_w, fc2_b);

    int grid = (n + 255) / 256;
    lstm_actor_kernel<<<grid, 256, SMEM_BYTES>>>(obs, (float*)d_out, n);
}